// round 3
// baseline (speedup 1.0000x reference)
#include <cuda_runtime.h>
#include <cstdint>

// ---------------- problem constants ----------------
#define BSZ   4
#define TLEN  2048
#define DM    1024
#define DI    2048      // d_inner
#define DS    64        // d_state
#define NCONV 4
#define NTOK  (BSZ*TLEN)   // 8192

// ---------------- scratch: __device__ globals, referenced directly in kernels ----
__device__ float g_arena[NTOK * DM];             // phase A: xn ; phase B: hc
__device__ float g_xr   [(size_t)NTOK * 2 * DI]; // xp | res   128 MB
__device__ float g_xc   [(size_t)NTOK * DI];     // conv+silu, later y  64 MB
__device__ float g_bc   [NTOK * 2 * DS];         // B | C
__device__ float g_dtsum[NTOK];
__device__ float g_ys   [NTOK];

#define g_xn g_arena     // [NTOK*DM],  live LN .. gemm1
#define g_hc g_arena     // [NTOK*DS],  live scan .. ysum (after gemm1 dead)

// buffer selectors for the GEMM template (device-side constexpr pointer pick)
#define SEL_XN 0
#define SEL_XC 1
#define SEL_XR 2
#define SEL_BC 3
#define SEL_PARAM 4

__device__ __forceinline__ float silu(float v) {
    return v / (1.0f + expf(-v));
}

// ---------------- LayerNorm: x -> g_xn ----------------
__global__ void ln_kernel(const float* __restrict__ x,
                          const float* __restrict__ g,
                          const float* __restrict__ b) {
    int row = blockIdx.x;
    const float* xp = x + (size_t)row * DM;
    float s = 0.f, s2 = 0.f;
    for (int i = threadIdx.x; i < DM; i += 256) {
        float v = xp[i];
        s += v; s2 += v * v;
    }
    for (int o = 16; o > 0; o >>= 1) {
        s  += __shfl_xor_sync(0xffffffffu, s, o);
        s2 += __shfl_xor_sync(0xffffffffu, s2, o);
    }
    __shared__ float sh[8], sh2[8];
    int w = threadIdx.x >> 5, l = threadIdx.x & 31;
    if (l == 0) { sh[w] = s; sh2[w] = s2; }
    __syncthreads();
    float ts = 0.f, ts2 = 0.f;
#pragma unroll
    for (int i = 0; i < 8; i++) { ts += sh[i]; ts2 += sh2[i]; }
    float mean = ts * (1.0f / DM);
    float var  = ts2 * (1.0f / DM) - mean * mean;
    float rstd = rsqrtf(var + 1e-5f);
    float* outp = g_xn + (size_t)row * DM;
    for (int i = threadIdx.x; i < DM; i += 256) {
        float v = xp[i];
        outp[i] = (v - mean) * rstd * g[i] + b[i];
    }
}

// ---------------- tiled SGEMM, scratch selected by template ----------------
// C[M,N] = A[M,K] @ B[K,N]  (row-major; M%128==0, N%128==0, K%16==0)
// ASEL: which scratch buffer is A. CSEL: which buffer is C (SEL_PARAM -> Cp).
// EPI: 0 = store C
//      2 = softplus(acc + bias[n]) row-reduced into g_dtsum[row] (no C store)
//      3 = store C = acc + add[row*N+n]
template <int EPI, int ASEL, int CSEL>
__global__ __launch_bounds__(256, 2)
void gemm_kernel(const float* __restrict__ Bw,
                 float* __restrict__ Cp, int M, int N, int K,
                 const float* __restrict__ bias,
                 const float* __restrict__ add) {
    const float* A = (ASEL == SEL_XN) ? g_xn : g_xc;
    float* C = (CSEL == SEL_XR) ? g_xr
             : (CSEL == SEL_BC) ? g_bc
             : Cp;

    const int BM = 128, BN = 128, BK = 16, TM = 8, TN = 8;
    __shared__ float As[BK][BM];
    __shared__ float Bs[BK][BN];

    int bx = blockIdx.x;              // N tile
    int by = blockIdx.y;              // M tile
    int tid = threadIdx.x;
    int tx = tid & 15;
    int ty = tid >> 4;

    const float* Ab = A + (size_t)by * BM * K;
    const float* Bb = Bw + (size_t)bx * BN;

    int arow  = tid >> 2;             // 0..63
    int acol4 = tid & 3;
    int brow  = tid >> 5;             // 0..7
    int bcol4 = tid & 31;             // 0..31

    float acc[TM][TN];
#pragma unroll
    for (int i = 0; i < TM; i++)
#pragma unroll
        for (int j = 0; j < TN; j++) acc[i][j] = 0.f;

    for (int k0 = 0; k0 < K; k0 += BK) {
#pragma unroll
        for (int r = 0; r < 2; r++) {
            float4 v = *(const float4*)(Ab + (size_t)(arow + 64 * r) * K + k0 + acol4 * 4);
            As[acol4 * 4 + 0][arow + 64 * r] = v.x;
            As[acol4 * 4 + 1][arow + 64 * r] = v.y;
            As[acol4 * 4 + 2][arow + 64 * r] = v.z;
            As[acol4 * 4 + 3][arow + 64 * r] = v.w;
        }
#pragma unroll
        for (int r = 0; r < 2; r++) {
            float4 v = *(const float4*)(Bb + (size_t)(k0 + brow + 8 * r) * N + bcol4 * 4);
            *(float4*)&Bs[brow + 8 * r][bcol4 * 4] = v;
        }
        __syncthreads();

#pragma unroll
        for (int kk = 0; kk < BK; kk++) {
            float ra[TM], rb[TN];
            float4 a0 = *(const float4*)&As[kk][ty * TM];
            float4 a1 = *(const float4*)&As[kk][ty * TM + 4];
            ra[0]=a0.x; ra[1]=a0.y; ra[2]=a0.z; ra[3]=a0.w;
            ra[4]=a1.x; ra[5]=a1.y; ra[6]=a1.z; ra[7]=a1.w;
            float4 b0 = *(const float4*)&Bs[kk][tx * TN];
            float4 b1 = *(const float4*)&Bs[kk][tx * TN + 4];
            rb[0]=b0.x; rb[1]=b0.y; rb[2]=b0.z; rb[3]=b0.w;
            rb[4]=b1.x; rb[5]=b1.y; rb[6]=b1.z; rb[7]=b1.w;
#pragma unroll
            for (int i = 0; i < TM; i++)
#pragma unroll
                for (int j = 0; j < TN; j++)
                    acc[i][j] += ra[i] * rb[j];
        }
        __syncthreads();
    }

    int row0 = by * BM + ty * TM;
    int col0 = bx * BN + tx * TN;

    if (EPI == 0) {
#pragma unroll
        for (int i = 0; i < TM; i++) {
            float4 v0 = make_float4(acc[i][0], acc[i][1], acc[i][2], acc[i][3]);
            float4 v1 = make_float4(acc[i][4], acc[i][5], acc[i][6], acc[i][7]);
            *(float4*)(C + (size_t)(row0 + i) * N + col0)     = v0;
            *(float4*)(C + (size_t)(row0 + i) * N + col0 + 4) = v1;
        }
    } else if (EPI == 3) {
#pragma unroll
        for (int i = 0; i < TM; i++) {
            const float* ap = add + (size_t)(row0 + i) * N + col0;
            float4 x0 = *(const float4*)(ap);
            float4 x1 = *(const float4*)(ap + 4);
            float4 v0 = make_float4(acc[i][0]+x0.x, acc[i][1]+x0.y, acc[i][2]+x0.z, acc[i][3]+x0.w);
            float4 v1 = make_float4(acc[i][4]+x1.x, acc[i][5]+x1.y, acc[i][6]+x1.z, acc[i][7]+x1.w);
            *(float4*)(C + (size_t)(row0 + i) * N + col0)     = v0;
            *(float4*)(C + (size_t)(row0 + i) * N + col0 + 4) = v1;
        }
    } else if (EPI == 2) {
        __shared__ float redsh[BM][16];
#pragma unroll
        for (int i = 0; i < TM; i++) {
            float s = 0.f;
#pragma unroll
            for (int j = 0; j < TN; j++) {
                float v = acc[i][j] + bias[col0 + j];
                float sp = (v > 20.f) ? v : log1pf(expf(v));
                s += sp;
            }
            redsh[ty * TM + i][tx] = s;
        }
        __syncthreads();
        if (tid < BM) {
            float s = 0.f;
#pragma unroll
            for (int c = 0; c < 16; c++) s += redsh[tid][c];
            atomicAdd(&g_dtsum[by * BM + tid], s);
        }
    }
}

// ---------------- depthwise causal conv + SiLU: g_xr[:, :DI] -> g_xc ----------------
__global__ void conv_kernel(const float* __restrict__ cw,
                            const float* __restrict__ cb) {
    int idx = blockIdx.x * 256 + threadIdx.x;
    if (idx >= NTOK * DI) return;
    int d   = idx & (DI - 1);
    int row = idx / DI;          // b*T + t
    int t   = row & (TLEN - 1);
    float acc = cb[d];
#pragma unroll
    for (int k = 0; k < NCONV; k++) {
        int tt = t + k - (NCONV - 1);
        if (tt >= 0)
            acc += cw[d * NCONV + k] * g_xr[(size_t)(row + k - (NCONV - 1)) * (2 * DI) + d];
    }
    g_xc[idx] = silu(acc);
}

// ---------------- zero dtsum ----------------
__global__ void zero_kernel() {
    int idx = blockIdx.x * 256 + threadIdx.x;
    if (idx < NTOK) g_dtsum[idx] = 0.f;
}

// ---------------- SSM scan: 256 independent scalar chains ----------------
__global__ void scan_kernel(const float* __restrict__ A_log) {
    int tid = threadIdx.x;
    int s = tid & 63;
    int b = tid >> 6;
    float Aval = -expf(A_log[s]);
    int base = b * TLEN;
    float h = 0.f;
    float nb = g_bc[(size_t)base * 2 * DS + s];
    float nc = g_bc[(size_t)base * 2 * DS + DS + s];
    float nd = g_dtsum[base];
    for (int t = 0; t < TLEN; t++) {
        float bv = nb, cv = nc, dv = nd;
        if (t + 1 < TLEN) {
            int r = base + t + 1;
            nb = g_bc[(size_t)r * 2 * DS + s];
            nc = g_bc[(size_t)r * 2 * DS + DS + s];
            nd = g_dtsum[r];
        }
        float a = expf(dv * (1.0f / DI) * Aval);
        h = h * a + bv;
        g_hc[(size_t)(base + t) * DS + s] = h * cv;
    }
}

// ---------------- ys[row] = sum_s hc[row][s] ----------------
__global__ void ysum_kernel() {
    int w = threadIdx.x >> 5, l = threadIdx.x & 31;
    int row = blockIdx.x * 8 + w;
    float v = g_hc[(size_t)row * DS + l] + g_hc[(size_t)row * DS + 32 + l];
    for (int o = 16; o > 0; o >>= 1) v += __shfl_xor_sync(0xffffffffu, v, o);
    if (l == 0) g_ys[row] = v;
}

// ---------------- y = (ys + D*xc) * silu(res), in place over g_xc ----------------
__global__ void ymix_kernel(const float* __restrict__ Dv) {
    int idx = blockIdx.x * 256 + threadIdx.x;
    if (idx >= NTOK * DI) return;
    int d   = idx & (DI - 1);
    int row = idx / DI;
    float res = g_xr[(size_t)row * 2 * DI + DI + d];
    g_xc[idx] = (g_ys[row] + Dv[d] * g_xc[idx]) * silu(res);
}

// ---------------- host: pure launches, zero CUDA API calls, zero state ----------------
extern "C" void kernel_launch(void* const* d_in, const int* in_sizes, int n_in,
                              void* d_out, int out_size) {
    const float* x      = (const float*)d_in[0];
    const float* ln_g   = (const float*)d_in[1];
    const float* ln_b   = (const float*)d_in[2];
    const float* W_in   = (const float*)d_in[3];
    const float* conv_w = (const float*)d_in[4];
    const float* conv_b = (const float*)d_in[5];
    const float* W_x    = (const float*)d_in[6];
    const float* W_dt   = (const float*)d_in[7];
    const float* b_dt   = (const float*)d_in[8];
    const float* A_log  = (const float*)d_in[9];
    const float* Dv     = (const float*)d_in[10];
    const float* W_out  = (const float*)d_in[11];
    float* out = (float*)d_out;

    // 1. LayerNorm -> g_xn
    ln_kernel<<<NTOK, 256>>>(x, ln_g, ln_b);

    // 2. g_xr = g_xn @ W_in   [8192,4096] = [8192,1024] @ [1024,4096]
    gemm_kernel<0, SEL_XN, SEL_XR><<<dim3(2 * DI / 128, NTOK / 128), 256>>>(
        W_in, nullptr, NTOK, 2 * DI, DM, nullptr, nullptr);

    // 3. depthwise conv + silu -> g_xc
    conv_kernel<<<(NTOK * DI) / 256, 256>>>(conv_w, conv_b);

    // 4. g_bc = g_xc @ W_x    [8192,128] = [8192,2048] @ [2048,128]
    gemm_kernel<0, SEL_XC, SEL_BC><<<dim3(1, NTOK / 128), 256>>>(
        W_x, nullptr, NTOK, 2 * DS, DI, nullptr, nullptr);

    // 5. g_dtsum[row] = sum_n softplus((g_xc @ W_dt)[row,n] + b_dt[n])
    zero_kernel<<<NTOK / 256, 256>>>();
    gemm_kernel<2, SEL_XC, SEL_PARAM><<<dim3(DI / 128, NTOK / 128), 256>>>(
        W_dt, nullptr, NTOK, DI, DI, b_dt, nullptr);

    // 6. sequential SSM scan (g_xn dead; arena reused as g_hc)
    scan_kernel<<<1, 256>>>(A_log);

    // 7. ys[row] = sum_s h*C
    ysum_kernel<<<NTOK / 8, 256>>>();

    // 8. y = (ys + D*xc) * silu(res)   (in place over g_xc)
    ymix_kernel<<<(NTOK * DI) / 256, 256>>>(Dv);

    // 9. out = y @ W_out + x  [8192,1024]
    gemm_kernel<3, SEL_XC, SEL_PARAM><<<dim3(DM / 128, NTOK / 128), 256>>>(
        W_out, out, NTOK, DM, DI, nullptr, x);
}

// round 4
// speedup vs baseline: 2.3127x; 2.3127x over previous
#include <cuda_runtime.h>
#include <cstdint>

// ---------------- problem constants ----------------
#define BSZ   4
#define TLEN  2048
#define DM    1024
#define DI    2048      // d_inner
#define DS    64        // d_state
#define NCONV 4
#define NTOK  (BSZ*TLEN)   // 8192

// ---------------- scratch ----------------
__device__ float g_arena[NTOK * DM];             // phase A: xn ; phase B: hc
__device__ float g_xr   [(size_t)NTOK * 2 * DI]; // xp | res
__device__ float g_xc   [(size_t)NTOK * DI];     // conv+silu, later y
__device__ float g_bc   [NTOK * 2 * DS];         // B | C (atomic accumulated)
__device__ float g_dtsum[NTOK];
__device__ float g_ys   [NTOK];

#define g_xn g_arena
#define g_hc g_arena

#define SEL_XN 0
#define SEL_XC 1
#define SEL_XR 2
#define SEL_BC 3
#define SEL_PARAM 4

__device__ __forceinline__ float silu(float v) { return v / (1.0f + expf(-v)); }

__device__ __forceinline__ uint32_t f2tf32(float f) {
    uint32_t r; asm("cvt.rna.tf32.f32 %0, %1;" : "=r"(r) : "f"(f)); return r;
}
__device__ __forceinline__ void cp16(void* smem, const void* g) {
    uint32_t s = (uint32_t)__cvta_generic_to_shared(smem);
    asm volatile("cp.async.cg.shared.global [%0], [%1], 16;\n" :: "r"(s), "l"(g));
}
__device__ __forceinline__ void cp_commit() { asm volatile("cp.async.commit_group;\n"); }
template <int N>
__device__ __forceinline__ void cp_wait() { asm volatile("cp.async.wait_group %0;\n" :: "n"(N)); }

__device__ __forceinline__ void mma_tf32(float& c0, float& c1, float& c2, float& c3,
                                         uint32_t a0, uint32_t a1, uint32_t a2, uint32_t a3,
                                         uint32_t b0, uint32_t b1) {
    asm volatile(
        "mma.sync.aligned.m16n8k8.row.col.f32.tf32.tf32.f32 "
        "{%0,%1,%2,%3}, {%4,%5,%6,%7}, {%8,%9}, {%0,%1,%2,%3};\n"
        : "+f"(c0), "+f"(c1), "+f"(c2), "+f"(c3)
        : "r"(a0), "r"(a1), "r"(a2), "r"(a3), "r"(b0), "r"(b1));
}

// ---------------- LayerNorm: x -> g_xn ----------------
__global__ void ln_kernel(const float* __restrict__ x,
                          const float* __restrict__ g,
                          const float* __restrict__ b) {
    int row = blockIdx.x;
    const float* xp = x + (size_t)row * DM;
    float s = 0.f, s2 = 0.f;
    for (int i = threadIdx.x; i < DM; i += 256) {
        float v = xp[i]; s += v; s2 += v * v;
    }
    for (int o = 16; o > 0; o >>= 1) {
        s  += __shfl_xor_sync(0xffffffffu, s, o);
        s2 += __shfl_xor_sync(0xffffffffu, s2, o);
    }
    __shared__ float sh[8], sh2[8];
    int w = threadIdx.x >> 5, l = threadIdx.x & 31;
    if (l == 0) { sh[w] = s; sh2[w] = s2; }
    __syncthreads();
    float ts = 0.f, ts2 = 0.f;
#pragma unroll
    for (int i = 0; i < 8; i++) { ts += sh[i]; ts2 += sh2[i]; }
    float mean = ts * (1.0f / DM);
    float var  = ts2 * (1.0f / DM) - mean * mean;
    float rstd = rsqrtf(var + 1e-5f);
    float* outp = g_xn + (size_t)row * DM;
    for (int i = threadIdx.x; i < DM; i += 256) {
        float v = xp[i];
        outp[i] = (v - mean) * rstd * g[i] + b[i];
    }
}

// ---------------- TF32 tensor-core GEMM ----------------
// C[M,N] = A[M,K] @ B[K,N], row-major. BM=BN=128, BK=16, 256 thr, 8 warps (4Mx2N),
// warp tile 32x64, mma m16n8k8. cp.async double-buffered.
// EPI: 0 store | 2 softplus+bias row-reduce -> g_dtsum | 3 store acc+add | 4 atomicAdd store
template <int EPI, int ASEL, int CSEL, int KSPLIT>
__global__ __launch_bounds__(256, 2)
void gemm_tc(const float* __restrict__ Bw, float* __restrict__ Cp,
             int M, int N, int K,
             const float* __restrict__ bias, const float* __restrict__ add) {
    const float* A = (ASEL == SEL_XN) ? g_xn : g_xc;
    float* C = (CSEL == SEL_XR) ? g_xr : (CSEL == SEL_BC) ? g_bc : Cp;

    __shared__ float As[2][128][20];   // [m][k], row stride 20 (conflict-free)
    __shared__ float Bs[2][16][132];   // [k][n], row stride 132

    const int tid  = threadIdx.x;
    const int lane = tid & 31;
    const int warp = tid >> 5;
    const int wm   = warp >> 1;        // 0..3
    const int wn   = warp & 1;         // 0..1
    const int bx = blockIdx.x, by = blockIdx.y;

    const int kchunk = K / KSPLIT;
    const int kbeg   = blockIdx.z * kchunk;
    const int nslab  = kchunk / 16;

    // A load coords: 2 x 16B per thread per slab
    const int arow  = tid >> 2;        // 0..63
    const int acol4 = (tid & 3) * 4;   // 0,4,8,12
    const float* Abase = A + (size_t)(by * 128) * K + kbeg;
    // B load coords: chunks tid and tid+256
    const float* Bbase = Bw + (size_t)kbeg * N + bx * 128;

    float acc[2][8][4];
#pragma unroll
    for (int i = 0; i < 2; i++)
#pragma unroll
        for (int j = 0; j < 8; j++)
#pragma unroll
            for (int c = 0; c < 4; c++) acc[i][j][c] = 0.f;

    auto issue = [&](int slab, int stage) {
        const float* Ab = Abase + slab * 16;
#pragma unroll
        for (int r = 0; r < 2; r++) {
            int row = arow + 64 * r;
            cp16(&As[stage][row][acol4], Ab + (size_t)row * K + acol4);
        }
        const float* Bb = Bbase + (size_t)(slab * 16) * N;
#pragma unroll
        for (int r = 0; r < 2; r++) {
            int c = tid + 256 * r;
            int row = c >> 5, col4 = (c & 31) * 4;
            cp16(&Bs[stage][row][col4], Bb + (size_t)row * N + col4);
        }
        cp_commit();
    };

    issue(0, 0);
    for (int s = 0; s < nslab; s++) {
        int stage = s & 1;
        if (s + 1 < nslab) issue(s + 1, stage ^ 1);
        if (s + 1 < nslab) cp_wait<1>(); else cp_wait<0>();
        __syncthreads();

#pragma unroll
        for (int ks = 0; ks < 2; ks++) {
            int kk = ks * 8 + (lane & 3);
            uint32_t af[2][4];
#pragma unroll
            for (int mt = 0; mt < 2; mt++) {
                int mrow = wm * 32 + mt * 16 + (lane >> 2);
                af[mt][0] = f2tf32(As[stage][mrow    ][kk    ]);
                af[mt][1] = f2tf32(As[stage][mrow + 8][kk    ]);
                af[mt][2] = f2tf32(As[stage][mrow    ][kk + 4]);
                af[mt][3] = f2tf32(As[stage][mrow + 8][kk + 4]);
            }
            uint32_t bf[8][2];
#pragma unroll
            for (int nt = 0; nt < 8; nt++) {
                int n = wn * 64 + nt * 8 + (lane >> 2);
                bf[nt][0] = f2tf32(Bs[stage][ks * 8 + (lane & 3)    ][n]);
                bf[nt][1] = f2tf32(Bs[stage][ks * 8 + (lane & 3) + 4][n]);
            }
#pragma unroll
            for (int mt = 0; mt < 2; mt++)
#pragma unroll
                for (int nt = 0; nt < 8; nt++)
                    mma_tf32(acc[mt][nt][0], acc[mt][nt][1], acc[mt][nt][2], acc[mt][nt][3],
                             af[mt][0], af[mt][1], af[mt][2], af[mt][3],
                             bf[nt][0], bf[nt][1]);
        }
        __syncthreads();
    }

    // epilogue: row(mt,h) = by*128 + wm*32 + mt*16 + h*8 + (lane>>2)
    //           col(nt,c) = bx*128 + wn*64 + nt*8  + 2*(lane&3) + c
    if (EPI == 2) {
#pragma unroll
        for (int mt = 0; mt < 2; mt++)
#pragma unroll
            for (int h = 0; h < 2; h++) {
                float s = 0.f;
#pragma unroll
                for (int nt = 0; nt < 8; nt++)
#pragma unroll
                    for (int c = 0; c < 2; c++) {
                        int col = bx * 128 + wn * 64 + nt * 8 + 2 * (lane & 3) + c;
                        float v = acc[mt][nt][2 * h + c] + bias[col];
                        s += (v > 20.f) ? v : log1pf(expf(v));
                    }
                s += __shfl_xor_sync(0xffffffffu, s, 1);
                s += __shfl_xor_sync(0xffffffffu, s, 2);
                if ((lane & 3) == 0) {
                    int row = by * 128 + wm * 32 + mt * 16 + h * 8 + (lane >> 2);
                    atomicAdd(&g_dtsum[row], s);
                }
            }
    } else {
#pragma unroll
        for (int mt = 0; mt < 2; mt++)
#pragma unroll
            for (int h = 0; h < 2; h++) {
                int row = by * 128 + wm * 32 + mt * 16 + h * 8 + (lane >> 2);
#pragma unroll
                for (int nt = 0; nt < 8; nt++) {
                    int col = bx * 128 + wn * 64 + nt * 8 + 2 * (lane & 3);
                    float v0 = acc[mt][nt][2 * h + 0];
                    float v1 = acc[mt][nt][2 * h + 1];
                    if (EPI == 3) {
                        const float* ap = add + (size_t)row * N + col;
                        v0 += ap[0]; v1 += ap[1];
                    }
                    if (EPI == 4) {
                        atomicAdd(&C[(size_t)row * N + col],     v0);
                        atomicAdd(&C[(size_t)row * N + col + 1], v1);
                    } else {
                        float2* cp2 = (float2*)(C + (size_t)row * N + col);
                        *cp2 = make_float2(v0, v1);
                    }
                }
            }
    }
}

// ---------------- depthwise causal conv + SiLU ----------------
__global__ void conv_kernel(const float* __restrict__ cw,
                            const float* __restrict__ cb) {
    int idx = blockIdx.x * 256 + threadIdx.x;
    if (idx >= NTOK * DI) return;
    int d   = idx & (DI - 1);
    int row = idx / DI;
    int t   = row & (TLEN - 1);
    float acc = cb[d];
#pragma unroll
    for (int k = 0; k < NCONV; k++) {
        int tt = t + k - (NCONV - 1);
        if (tt >= 0)
            acc += cw[d * NCONV + k] * g_xr[(size_t)(row + k - (NCONV - 1)) * (2 * DI) + d];
    }
    g_xc[idx] = silu(acc);
}

// ---------------- zero dtsum + bc (atomic targets) ----------------
__global__ void zero_kernel() {
    int idx = blockIdx.x * 256 + threadIdx.x;
    if (idx < NTOK) g_dtsum[idx] = 0.f;
    if (idx < NTOK * 2 * DS) g_bc[idx] = 0.f;
}

// ---------------- SSM scan: 256 independent scalar chains ----------------
__global__ void scan_kernel(const float* __restrict__ A_log) {
    int id = blockIdx.x * 32 + threadIdx.x;   // 0..255
    int s = id & 63;
    int b = id >> 6;
    float Aval = -expf(A_log[s]);
    int base = b * TLEN;
    float h = 0.f;
    float nb = g_bc[(size_t)base * 2 * DS + s];
    float nc = g_bc[(size_t)base * 2 * DS + DS + s];
    float nd = g_dtsum[base];
    for (int t = 0; t < TLEN; t++) {
        float bv = nb, cv = nc, dv = nd;
        if (t + 1 < TLEN) {
            int r = base + t + 1;
            nb = g_bc[(size_t)r * 2 * DS + s];
            nc = g_bc[(size_t)r * 2 * DS + DS + s];
            nd = g_dtsum[r];
        }
        float a = expf(dv * (1.0f / DI) * Aval);
        h = h * a + bv;
        g_hc[(size_t)(base + t) * DS + s] = h * cv;
    }
}

// ---------------- ys[row] = sum_s hc[row][s] ----------------
__global__ void ysum_kernel() {
    int w = threadIdx.x >> 5, l = threadIdx.x & 31;
    int row = blockIdx.x * 8 + w;
    float v = g_hc[(size_t)row * DS + l] + g_hc[(size_t)row * DS + 32 + l];
    for (int o = 16; o > 0; o >>= 1) v += __shfl_xor_sync(0xffffffffu, v, o);
    if (l == 0) g_ys[row] = v;
}

// ---------------- y = (ys + D*xc) * silu(res) ----------------
__global__ void ymix_kernel(const float* __restrict__ Dv) {
    int idx = blockIdx.x * 256 + threadIdx.x;
    if (idx >= NTOK * DI) return;
    int d   = idx & (DI - 1);
    int row = idx / DI;
    float res = g_xr[(size_t)row * 2 * DI + DI + d];
    g_xc[idx] = (g_ys[row] + Dv[d] * g_xc[idx]) * silu(res);
}

// ---------------- host: pure launches ----------------
extern "C" void kernel_launch(void* const* d_in, const int* in_sizes, int n_in,
                              void* d_out, int out_size) {
    const float* x      = (const float*)d_in[0];
    const float* ln_g   = (const float*)d_in[1];
    const float* ln_b   = (const float*)d_in[2];
    const float* W_in   = (const float*)d_in[3];
    const float* conv_w = (const float*)d_in[4];
    const float* conv_b = (const float*)d_in[5];
    const float* W_x    = (const float*)d_in[6];
    const float* W_dt   = (const float*)d_in[7];
    const float* b_dt   = (const float*)d_in[8];
    const float* A_log  = (const float*)d_in[9];
    const float* Dv     = (const float*)d_in[10];
    const float* W_out  = (const float*)d_in[11];
    float* out = (float*)d_out;

    // 1. LayerNorm -> g_xn
    ln_kernel<<<NTOK, 256>>>(x, ln_g, ln_b);

    // 2. g_xr = g_xn @ W_in   [8192,4096]x[1024]
    gemm_tc<0, SEL_XN, SEL_XR, 1><<<dim3(2 * DI / 128, NTOK / 128, 1), 256>>>(
        W_in, nullptr, NTOK, 2 * DI, DM, nullptr, nullptr);

    // 3. conv + silu -> g_xc ; zero atomic targets in parallel stream order
    conv_kernel<<<(NTOK * DI) / 256, 256>>>(conv_w, conv_b);
    zero_kernel<<<(NTOK * 2 * DS) / 256, 256>>>();

    // 4. g_bc += g_xc @ W_x   [8192,128]x[2048], split-K=8
    gemm_tc<4, SEL_XC, SEL_BC, 8><<<dim3(1, NTOK / 128, 8), 256>>>(
        W_x, nullptr, NTOK, 2 * DS, DI, nullptr, nullptr);

    // 5. g_dtsum[row] += sum_n softplus((g_xc @ W_dt)[row,n] + b_dt[n])
    gemm_tc<2, SEL_XC, SEL_PARAM, 1><<<dim3(DI / 128, NTOK / 128, 1), 256>>>(
        W_dt, nullptr, NTOK, DI, DI, b_dt, nullptr);

    // 6. SSM scan
    scan_kernel<<<8, 32>>>(A_log);

    // 7. ys
    ysum_kernel<<<NTOK / 8, 256>>>();

    // 8. gate/mix
    ymix_kernel<<<(NTOK * DI) / 256, 256>>>(Dv);

    // 9. out = y @ W_out + x  [8192,1024]x[2048]
    gemm_tc<3, SEL_XC, SEL_PARAM, 1><<<dim3(DM / 128, NTOK / 128, 1), 256>>>(
        W_out, out, NTOK, DM, DI, nullptr, x);
}

// round 5
// speedup vs baseline: 2.4740x; 1.0697x over previous
#include <cuda_runtime.h>
#include <cstdint>

// ---------------- problem constants ----------------
#define BSZ   4
#define TLEN  2048
#define DM    1024
#define DI    2048      // d_inner
#define DS    64        // d_state
#define NCONV 4
#define NTOK  (BSZ*TLEN)   // 8192

// ---------------- scratch ----------------
__device__ float g_arena[NTOK * DM];             // phase A: xn ; phase B: hc
__device__ float g_xr   [(size_t)NTOK * 2 * DI]; // xp | res
__device__ float g_xc   [(size_t)NTOK * DI];     // conv+silu (tf32-rounded), later y
__device__ float g_bc   [NTOK * 2 * DS];         // B | C (atomic accumulated)
__device__ float g_dtsum[NTOK];
__device__ float g_ys   [NTOK];
// tf32-rounded weight copies
__device__ float g_w_in [DM * 2 * DI];           // 16 MB
__device__ float g_w_x  [DI * 2 * DS];           //  1 MB
__device__ float g_w_dt [DI * DI];               // 16 MB
__device__ float g_w_out[DI * DM];               //  8 MB

#define g_xn g_arena
#define g_hc g_arena

#define SEL_XN 0
#define SEL_XC 1
#define SEL_XR 2
#define SEL_BC 3
#define SEL_PARAM 4
#define WSEL_IN  0
#define WSEL_X   1
#define WSEL_DT  2
#define WSEL_OUT 3

__device__ __forceinline__ float silu(float v) { return v / (1.0f + expf(-v)); }

__device__ __forceinline__ float tf32r(float f) {
    uint32_t r; asm("cvt.rna.tf32.f32 %0, %1;" : "=r"(r) : "f"(f));
    return __uint_as_float(r);
}
__device__ __forceinline__ void cp16(void* smem, const void* g) {
    uint32_t s = (uint32_t)__cvta_generic_to_shared(smem);
    asm volatile("cp.async.cg.shared.global [%0], [%1], 16;\n" :: "r"(s), "l"(g));
}
__device__ __forceinline__ void cp_commit() { asm volatile("cp.async.commit_group;\n"); }
template <int N>
__device__ __forceinline__ void cp_wait() { asm volatile("cp.async.wait_group %0;\n" :: "n"(N)); }

__device__ __forceinline__ void mma_tf32(float& c0, float& c1, float& c2, float& c3,
                                         uint32_t a0, uint32_t a1, uint32_t a2, uint32_t a3,
                                         uint32_t b0, uint32_t b1) {
    asm volatile(
        "mma.sync.aligned.m16n8k8.row.col.f32.tf32.tf32.f32 "
        "{%0,%1,%2,%3}, {%4,%5,%6,%7}, {%8,%9}, {%0,%1,%2,%3};\n"
        : "+f"(c0), "+f"(c1), "+f"(c2), "+f"(c3)
        : "r"(a0), "r"(a1), "r"(a2), "r"(a3), "r"(b0), "r"(b1));
}

// ---------------- one-shot weight rounding to tf32 ----------------
__global__ void round_w_kernel(const float* __restrict__ win,
                               const float* __restrict__ wx,
                               const float* __restrict__ wdt,
                               const float* __restrict__ wout) {
    int idx = blockIdx.x * 256 + threadIdx.x;           // grid covers 4M
    g_w_in[idx] = tf32r(win[idx]);
    g_w_dt[idx] = tf32r(wdt[idx]);
    if (idx < DI * DM)     g_w_out[idx] = tf32r(wout[idx]);
    if (idx < DI * 2 * DS) g_w_x[idx]   = tf32r(wx[idx]);
}

// ---------------- LayerNorm: x -> g_xn (tf32-rounded) ----------------
__global__ void ln_kernel(const float* __restrict__ x,
                          const float* __restrict__ g,
                          const float* __restrict__ b) {
    int row = blockIdx.x;
    const float* xp = x + (size_t)row * DM;
    float s = 0.f, s2 = 0.f;
    for (int i = threadIdx.x; i < DM; i += 256) {
        float v = xp[i]; s += v; s2 += v * v;
    }
    for (int o = 16; o > 0; o >>= 1) {
        s  += __shfl_xor_sync(0xffffffffu, s, o);
        s2 += __shfl_xor_sync(0xffffffffu, s2, o);
    }
    __shared__ float sh[8], sh2[8];
    int w = threadIdx.x >> 5, l = threadIdx.x & 31;
    if (l == 0) { sh[w] = s; sh2[w] = s2; }
    __syncthreads();
    float ts = 0.f, ts2 = 0.f;
#pragma unroll
    for (int i = 0; i < 8; i++) { ts += sh[i]; ts2 += sh2[i]; }
    float mean = ts * (1.0f / DM);
    float var  = ts2 * (1.0f / DM) - mean * mean;
    float rstd = rsqrtf(var + 1e-5f);
    float* outp = g_xn + (size_t)row * DM;
    for (int i = threadIdx.x; i < DM; i += 256) {
        float v = xp[i];
        outp[i] = tf32r((v - mean) * rstd * g[i] + b[i]);
    }
}

// ---------------- TF32 tensor-core GEMM v2 ----------------
// 128 threads, 4 warps (2x2), warp tile 64x64, BM=BN=128, BK=16, double-buffered
// cp.async. Inputs pre-rounded to tf32 (no cvt in mainloop).
// EPI: 0 store | 2 softplus+bias row-reduce -> g_dtsum | 3 store acc+add | 4 atomicAdd
template <int EPI, int ASEL, int BSEL, int CSEL, int KSPLIT>
__global__ __launch_bounds__(128, 2)
void gemm_tc(float* __restrict__ Cp, int M, int N, int K,
             const float* __restrict__ bias, const float* __restrict__ add) {
    const float* A = (ASEL == SEL_XN) ? g_xn : g_xc;
    const float* Bw = (BSEL == WSEL_IN) ? g_w_in
                    : (BSEL == WSEL_X)  ? g_w_x
                    : (BSEL == WSEL_DT) ? g_w_dt : g_w_out;
    float* C = (CSEL == SEL_XR) ? g_xr : (CSEL == SEL_BC) ? g_bc : Cp;

    __shared__ float As[2][128][20];   // [m][k], stride 20 -> conflict-free frag loads
    __shared__ float Bs[2][16][136];   // [k][n], stride 136 (mod 32 == 8) -> conflict-free

    const int tid  = threadIdx.x;
    const int lane = tid & 31;
    const int warp = tid >> 5;         // 0..3
    const int wm   = warp >> 1;        // 0..1
    const int wn   = warp & 1;         // 0..1
    const int bx = blockIdx.x, by = blockIdx.y;

    const int kchunk = K / KSPLIT;
    const int kbeg   = blockIdx.z * kchunk;
    const int nslab  = kchunk / 16;

    const float* Abase = A + (size_t)(by * 128) * K + kbeg;
    const float* Bbase = Bw + (size_t)kbeg * N + bx * 128;

    float acc[4][8][4];
#pragma unroll
    for (int i = 0; i < 4; i++)
#pragma unroll
        for (int j = 0; j < 8; j++)
#pragma unroll
            for (int c = 0; c < 4; c++) acc[i][j][c] = 0.f;

    auto issue = [&](int slab, int stage) {
        const float* Ab = Abase + slab * 16;
#pragma unroll
        for (int r = 0; r < 4; r++) {          // 512 chunks / 128 thr
            int c = tid + 128 * r;
            int row = c >> 2, col4 = (c & 3) * 4;
            cp16(&As[stage][row][col4], Ab + (size_t)row * K + col4);
        }
        const float* Bb = Bbase + (size_t)(slab * 16) * N;
#pragma unroll
        for (int r = 0; r < 4; r++) {          // 512 chunks / 128 thr
            int c = tid + 128 * r;
            int row = c >> 5, col4 = (c & 31) * 4;
            cp16(&Bs[stage][row][col4], Bb + (size_t)row * N + col4);
        }
        cp_commit();
    };

    issue(0, 0);
    for (int s = 0; s < nslab; s++) {
        int st = s & 1;
        if (s + 1 < nslab) { issue(s + 1, st ^ 1); cp_wait<1>(); }
        else               { cp_wait<0>(); }
        __syncthreads();

#pragma unroll
        for (int ks = 0; ks < 2; ks++) {
            const int kk = ks * 8 + (lane & 3);
            uint32_t af[4][4];
#pragma unroll
            for (int mt = 0; mt < 4; mt++) {
                int mrow = wm * 64 + mt * 16 + (lane >> 2);
                af[mt][0] = __float_as_uint(As[st][mrow    ][kk    ]);
                af[mt][1] = __float_as_uint(As[st][mrow + 8][kk    ]);
                af[mt][2] = __float_as_uint(As[st][mrow    ][kk + 4]);
                af[mt][3] = __float_as_uint(As[st][mrow + 8][kk + 4]);
            }
            uint32_t bf[8][2];
#pragma unroll
            for (int nt = 0; nt < 8; nt++) {
                int n = wn * 64 + nt * 8 + (lane >> 2);
                bf[nt][0] = __float_as_uint(Bs[st][kk    ][n]);
                bf[nt][1] = __float_as_uint(Bs[st][kk + 4][n]);
            }
#pragma unroll
            for (int mt = 0; mt < 4; mt++)
#pragma unroll
                for (int nt = 0; nt < 8; nt++)
                    mma_tf32(acc[mt][nt][0], acc[mt][nt][1], acc[mt][nt][2], acc[mt][nt][3],
                             af[mt][0], af[mt][1], af[mt][2], af[mt][3],
                             bf[nt][0], bf[nt][1]);
        }
        __syncthreads();
    }

    // row(mt,h) = by*128 + wm*64 + mt*16 + h*8 + (lane>>2)
    // col(nt,c) = bx*128 + wn*64 + nt*8  + 2*(lane&3) + c
    if (EPI == 2) {
#pragma unroll
        for (int mt = 0; mt < 4; mt++)
#pragma unroll
            for (int h = 0; h < 2; h++) {
                float s = 0.f;
#pragma unroll
                for (int nt = 0; nt < 8; nt++)
#pragma unroll
                    for (int c = 0; c < 2; c++) {
                        int col = bx * 128 + wn * 64 + nt * 8 + 2 * (lane & 3) + c;
                        float v = acc[mt][nt][2 * h + c] + bias[col];
                        s += (v > 20.f) ? v : log1pf(expf(v));
                    }
                s += __shfl_xor_sync(0xffffffffu, s, 1);
                s += __shfl_xor_sync(0xffffffffu, s, 2);
                if ((lane & 3) == 0) {
                    int row = by * 128 + wm * 64 + mt * 16 + h * 8 + (lane >> 2);
                    atomicAdd(&g_dtsum[row], s);
                }
            }
    } else {
#pragma unroll
        for (int mt = 0; mt < 4; mt++)
#pragma unroll
            for (int h = 0; h < 2; h++) {
                int row = by * 128 + wm * 64 + mt * 16 + h * 8 + (lane >> 2);
#pragma unroll
                for (int nt = 0; nt < 8; nt++) {
                    int col = bx * 128 + wn * 64 + nt * 8 + 2 * (lane & 3);
                    float v0 = acc[mt][nt][2 * h + 0];
                    float v1 = acc[mt][nt][2 * h + 1];
                    if (EPI == 3) {
                        const float* ap = add + (size_t)row * N + col;
                        v0 += ap[0]; v1 += ap[1];
                    }
                    if (EPI == 4) {
                        atomicAdd(&C[(size_t)row * N + col],     v0);
                        atomicAdd(&C[(size_t)row * N + col + 1], v1);
                    } else {
                        *(float2*)(C + (size_t)row * N + col) = make_float2(v0, v1);
                    }
                }
            }
    }
}

// ---------------- depthwise causal conv + SiLU (tf32-rounded out) ----------------
__global__ void conv_kernel(const float* __restrict__ cw,
                            const float* __restrict__ cb) {
    int idx = blockIdx.x * 256 + threadIdx.x;
    if (idx >= NTOK * DI) return;
    int d   = idx & (DI - 1);
    int row = idx / DI;
    int t   = row & (TLEN - 1);
    float acc = cb[d];
#pragma unroll
    for (int k = 0; k < NCONV; k++) {
        int tt = t + k - (NCONV - 1);
        if (tt >= 0)
            acc += cw[d * NCONV + k] * g_xr[(size_t)(row + k - (NCONV - 1)) * (2 * DI) + d];
    }
    g_xc[idx] = tf32r(silu(acc));
}

// ---------------- zero atomic targets ----------------
__global__ void zero_kernel() {
    int idx = blockIdx.x * 256 + threadIdx.x;
    if (idx < NTOK) g_dtsum[idx] = 0.f;
    if (idx < NTOK * 2 * DS) g_bc[idx] = 0.f;
}

// ---------------- SSM scan: 256 independent scalar chains ----------------
__global__ void scan_kernel(const float* __restrict__ A_log) {
    int id = blockIdx.x * 32 + threadIdx.x;
    int s = id & 63;
    int b = id >> 6;
    float Aval = -expf(A_log[s]);
    int base = b * TLEN;
    float h = 0.f;
    float nb = g_bc[(size_t)base * 2 * DS + s];
    float nc = g_bc[(size_t)base * 2 * DS + DS + s];
    float nd = g_dtsum[base];
    for (int t = 0; t < TLEN; t++) {
        float bv = nb, cv = nc, dv = nd;
        if (t + 1 < TLEN) {
            int r = base + t + 1;
            nb = g_bc[(size_t)r * 2 * DS + s];
            nc = g_bc[(size_t)r * 2 * DS + DS + s];
            nd = g_dtsum[r];
        }
        float a = expf(dv * (1.0f / DI) * Aval);
        h = h * a + bv;
        g_hc[(size_t)(base + t) * DS + s] = h * cv;
    }
}

// ---------------- ys[row] = sum_s hc[row][s] ----------------
__global__ void ysum_kernel() {
    int w = threadIdx.x >> 5, l = threadIdx.x & 31;
    int row = blockIdx.x * 8 + w;
    float v = g_hc[(size_t)row * DS + l] + g_hc[(size_t)row * DS + 32 + l];
    for (int o = 16; o > 0; o >>= 1) v += __shfl_xor_sync(0xffffffffu, v, o);
    if (l == 0) g_ys[row] = v;
}

// ---------------- y = (ys + D*xc) * silu(res), tf32-rounded, in place ----------------
__global__ void ymix_kernel(const float* __restrict__ Dv) {
    int idx = blockIdx.x * 256 + threadIdx.x;
    if (idx >= NTOK * DI) return;
    int d   = idx & (DI - 1);
    int row = idx / DI;
    float res = g_xr[(size_t)row * 2 * DI + DI + d];
    g_xc[idx] = tf32r((g_ys[row] + Dv[d] * g_xc[idx]) * silu(res));
}

// ---------------- host: pure launches ----------------
extern "C" void kernel_launch(void* const* d_in, const int* in_sizes, int n_in,
                              void* d_out, int out_size) {
    const float* x      = (const float*)d_in[0];
    const float* ln_g   = (const float*)d_in[1];
    const float* ln_b   = (const float*)d_in[2];
    const float* W_in   = (const float*)d_in[3];
    const float* conv_w = (const float*)d_in[4];
    const float* conv_b = (const float*)d_in[5];
    const float* W_x    = (const float*)d_in[6];
    const float* W_dt   = (const float*)d_in[7];
    const float* b_dt   = (const float*)d_in[8];
    const float* A_log  = (const float*)d_in[9];
    const float* Dv     = (const float*)d_in[10];
    const float* W_out  = (const float*)d_in[11];
    float* out = (float*)d_out;

    // 0. round weights to tf32 (covers 4M idx; W_in/W_dt full, others masked)
    round_w_kernel<<<(DM * 2 * DI) / 256, 256>>>(W_in, W_x, W_dt, W_out);

    // 1. LayerNorm -> g_xn (rounded)
    ln_kernel<<<NTOK, 256>>>(x, ln_g, ln_b);

    // 2. g_xr = xn @ W_in   [8192,4096]x[1024]
    gemm_tc<0, SEL_XN, WSEL_IN, SEL_XR, 1><<<dim3(2 * DI / 128, NTOK / 128, 1), 128>>>(
        nullptr, NTOK, 2 * DI, DM, nullptr, nullptr);

    // 3. conv + silu -> g_xc (rounded); zero atomic targets
    conv_kernel<<<(NTOK * DI) / 256, 256>>>(conv_w, conv_b);
    zero_kernel<<<(NTOK * 2 * DS) / 256, 256>>>();

    // 4. g_bc += xc @ W_x   [8192,128]x[2048], split-K=8
    gemm_tc<4, SEL_XC, WSEL_X, SEL_BC, 8><<<dim3(1, NTOK / 128, 8), 128>>>(
        nullptr, NTOK, 2 * DS, DI, nullptr, nullptr);

    // 5. g_dtsum[row] += sum_n softplus((xc @ W_dt)[row,n] + b_dt[n])
    gemm_tc<2, SEL_XC, WSEL_DT, SEL_PARAM, 1><<<dim3(DI / 128, NTOK / 128, 1), 128>>>(
        nullptr, NTOK, DI, DI, b_dt, nullptr);

    // 6. SSM scan
    scan_kernel<<<8, 32>>>(A_log);

    // 7. ys
    ysum_kernel<<<NTOK / 8, 256>>>();

    // 8. gate/mix -> g_xc (rounded)
    ymix_kernel<<<(NTOK * DI) / 256, 256>>>(Dv);

    // 9. out = y @ W_out + x  [8192,1024]x[2048]
    gemm_tc<3, SEL_XC, WSEL_OUT, SEL_PARAM, 1><<<dim3(DM / 128, NTOK / 128, 1), 128>>>(
        out, NTOK, DM, DI, nullptr, x);
}